// round 1
// baseline (speedup 1.0000x reference)
#include <cuda_runtime.h>

// WaveletSparsityPrior: 3-level Haar DWT sparsity loss, fully local to 8x8 tiles.
// Input: pred (64,1,1024,1024) fp32. Output: scalar fp32.
//
// j=1: band 512x512, level_idx=3, thr=BASE/4, weight 1/3
// j=2: band 256x256, level_idx=2, thr=BASE/2, weight 1/2
// j=3: band 128x128, level_idx=1, thr=BASE,   weight 1
// total = sum_j weight_j * (sum_{3 bands} mean(min(|c|,thr_j))) / 3

#define BASE_THR (50.0f / 255.0f)

#define BATCH 64
#define H 1024
#define W 1024

// per-level scale constants: weight_j / (3 * N_j)
// N1 = 64*512*512, N2 = 64*256*256, N3 = 64*128*128
__device__ __forceinline__ float quad_bands(float a, float b, float c, float d,
                                            float thr, float& ll)
{
    // a = x[2i,2j], b = x[2i,2j+1], c = x[2i+1,2j], d = x[2i+1,2j+1]
    ll        = (a + b + c + d) * 0.5f;
    float lh  = (b + d - a - c) * 0.5f;
    float hl  = (c + d - a - b) * 0.5f;
    float hh  = (a - b - c + d) * 0.5f;
    return fminf(fabsf(lh), thr) + fminf(fabsf(hl), thr) + fminf(fabsf(hh), thr);
}

__global__ void zero_out_kernel(float* out)
{
    out[0] = 0.0f;
}

__global__ __launch_bounds__(256, 4)
void wavelet_prior_kernel(const float* __restrict__ pred, float* __restrict__ out)
{
    const unsigned tid = blockIdx.x * blockDim.x + threadIdx.x;
    // one thread per 8x8 tile: 128x128 tiles per image, 64 images
    const unsigned bx = tid & 127u;          // tile col
    const unsigned by = (tid >> 7) & 127u;   // tile row
    const unsigned bb = tid >> 14;           // batch

    const float* base = pred + ((size_t)bb << 20) + (size_t)(by * 8u) * W + bx * 8u;

    const float t1 = BASE_THR * 0.25f;
    const float t2 = BASE_THR * 0.5f;
    const float t3 = BASE_THR;

    float s1 = 0.0f, s2 = 0.0f, s3 = 0.0f;
    float ll1[16];   // 4x4 level-1 LL

    #pragma unroll
    for (int r = 0; r < 4; ++r) {
        const float4 a0 = __ldg((const float4*)(base + (size_t)(2 * r)     * W));
        const float4 a1 = __ldg((const float4*)(base + (size_t)(2 * r)     * W + 4));
        const float4 b0 = __ldg((const float4*)(base + (size_t)(2 * r + 1) * W));
        const float4 b1 = __ldg((const float4*)(base + (size_t)(2 * r + 1) * W + 4));

        s1 += quad_bands(a0.x, a0.y, b0.x, b0.y, t1, ll1[r * 4 + 0]);
        s1 += quad_bands(a0.z, a0.w, b0.z, b0.w, t1, ll1[r * 4 + 1]);
        s1 += quad_bands(a1.x, a1.y, b1.x, b1.y, t1, ll1[r * 4 + 2]);
        s1 += quad_bands(a1.z, a1.w, b1.z, b1.w, t1, ll1[r * 4 + 3]);
    }

    float ll2[4];    // 2x2 level-2 LL
    #pragma unroll
    for (int r = 0; r < 2; ++r) {
        s2 += quad_bands(ll1[(2 * r) * 4 + 0], ll1[(2 * r) * 4 + 1],
                         ll1[(2 * r + 1) * 4 + 0], ll1[(2 * r + 1) * 4 + 1],
                         t2, ll2[r * 2 + 0]);
        s2 += quad_bands(ll1[(2 * r) * 4 + 2], ll1[(2 * r) * 4 + 3],
                         ll1[(2 * r + 1) * 4 + 2], ll1[(2 * r + 1) * 4 + 3],
                         t2, ll2[r * 2 + 1]);
    }

    float ll3;
    s3 += quad_bands(ll2[0], ll2[1], ll2[2], ll2[3], t3, ll3);
    (void)ll3;

    // weight_j / (3 * N_j)
    const float c1 = (1.0f / 3.0f) / (3.0f * (float)(BATCH * 512 * 512));
    const float c2 = 0.5f          / (3.0f * (float)(BATCH * 256 * 256));
    const float c3 = 1.0f          / (3.0f * (float)(BATCH * 128 * 128));

    float partial = c1 * s1 + c2 * s2 + c3 * s3;

    // warp reduce
    #pragma unroll
    for (int off = 16; off > 0; off >>= 1)
        partial += __shfl_xor_sync(0xFFFFFFFFu, partial, off);

    __shared__ float warp_sums[8];
    const int lane = threadIdx.x & 31;
    const int wid  = threadIdx.x >> 5;
    if (lane == 0) warp_sums[wid] = partial;
    __syncthreads();

    if (wid == 0) {
        float v = (lane < 8) ? warp_sums[lane] : 0.0f;
        #pragma unroll
        for (int off = 4; off > 0; off >>= 1)
            v += __shfl_xor_sync(0xFFFFFFFFu, v, off);
        if (lane == 0)
            atomicAdd(out, v);
    }
}

extern "C" void kernel_launch(void* const* d_in, const int* in_sizes, int n_in,
                              void* d_out, int out_size)
{
    const float* pred = (const float*)d_in[0];
    float* out = (float*)d_out;

    zero_out_kernel<<<1, 1>>>(out);

    const int total_tiles = BATCH * (H / 8) * (W / 8);   // 1,048,576
    const int threads = 256;
    const int blocks = total_tiles / threads;            // 4096
    wavelet_prior_kernel<<<blocks, threads>>>(pred, out);
}

// round 3
// speedup vs baseline: 1.0110x; 1.0110x over previous
#include <cuda_runtime.h>

// WaveletSparsityPrior: 3-level Haar DWT sparsity loss, fully local to 8x8 tiles.
// Input: pred (64,1,1024,1024) fp32. Output: scalar fp32.
//
// j=1: band 512x512, level_idx=3, thr=BASE/4, weight 1/3
// j=2: band 256x256, level_idx=2, thr=BASE/2, weight 1/2
// j=3: band 128x128, level_idx=1, thr=BASE,   weight 1
// total = sum_j weight_j * (sum_{3 bands} mean(min(|c|,thr_j))) / 3
//
// R2: incremental level-2 folding (halves live wavelet state) + 48-reg cap
// for 62.5% occupancy (was 64 regs / 46.6%). Goal: more loads in flight/SM.
// R3: identical resubmit — R2 bench died to a broker/container infra error
// before running; theory still untested.

#define BASE_THR (50.0f / 255.0f)

#define BATCH 64
#define H 1024
#define W 1024

__device__ __forceinline__ float quad_bands(float a, float b, float c, float d,
                                            float thr, float& ll)
{
    // a = x[2i,2j], b = x[2i,2j+1], c = x[2i+1,2j], d = x[2i+1,2j+1]
    ll        = (a + b + c + d) * 0.5f;
    float lh  = (b + d - a - c) * 0.5f;
    float hl  = (c + d - a - b) * 0.5f;
    float hh  = (a - b - c + d) * 0.5f;
    return fminf(fabsf(lh), thr) + fminf(fabsf(hl), thr) + fminf(fabsf(hh), thr);
}

__global__ void zero_out_kernel(float* out)
{
    out[0] = 0.0f;
}

__global__ __launch_bounds__(256, 5)
void wavelet_prior_kernel(const float* __restrict__ pred, float* __restrict__ out)
{
    const unsigned tid = blockIdx.x * blockDim.x + threadIdx.x;
    // one thread per 8x8 tile: 128x128 tiles per image, 64 images
    const unsigned bx = tid & 127u;          // tile col
    const unsigned by = (tid >> 7) & 127u;   // tile row
    const unsigned bb = tid >> 14;           // batch

    const float* base = pred + ((size_t)bb << 20) + (size_t)(by * 8u) * W + bx * 8u;

    const float t1 = BASE_THR * 0.25f;
    const float t2 = BASE_THR * 0.5f;
    const float t3 = BASE_THR;

    float s1 = 0.0f, s2 = 0.0f;
    float ll2[4];    // 2x2 level-2 LL

    #pragma unroll
    for (int half = 0; half < 2; ++half) {
        float ll1[8];   // 2 rows x 4 cols of level-1 LL (live only within this half)

        #pragma unroll
        for (int r = 0; r < 2; ++r) {
            const int row = half * 4 + 2 * r;
            const float4 a0 = __ldg((const float4*)(base + (size_t)row       * W));
            const float4 a1 = __ldg((const float4*)(base + (size_t)row       * W + 4));
            const float4 b0 = __ldg((const float4*)(base + (size_t)(row + 1) * W));
            const float4 b1 = __ldg((const float4*)(base + (size_t)(row + 1) * W + 4));

            s1 += quad_bands(a0.x, a0.y, b0.x, b0.y, t1, ll1[r * 4 + 0]);
            s1 += quad_bands(a0.z, a0.w, b0.z, b0.w, t1, ll1[r * 4 + 1]);
            s1 += quad_bands(a1.x, a1.y, b1.x, b1.y, t1, ll1[r * 4 + 2]);
            s1 += quad_bands(a1.z, a1.w, b1.z, b1.w, t1, ll1[r * 4 + 3]);
        }

        // fold this half's 2x4 level-1 LL into level-2 immediately
        s2 += quad_bands(ll1[0], ll1[1], ll1[4], ll1[5], t2, ll2[half * 2 + 0]);
        s2 += quad_bands(ll1[2], ll1[3], ll1[6], ll1[7], t2, ll2[half * 2 + 1]);
    }

    float ll3;
    const float s3 = quad_bands(ll2[0], ll2[1], ll2[2], ll2[3], t3, ll3);
    (void)ll3;

    // weight_j / (3 * N_j)
    const float c1 = (1.0f / 3.0f) / (3.0f * (float)(BATCH * 512 * 512));
    const float c2 = 0.5f          / (3.0f * (float)(BATCH * 256 * 256));
    const float c3 = 1.0f          / (3.0f * (float)(BATCH * 128 * 128));

    float partial = c1 * s1 + c2 * s2 + c3 * s3;

    // warp reduce
    #pragma unroll
    for (int off = 16; off > 0; off >>= 1)
        partial += __shfl_xor_sync(0xFFFFFFFFu, partial, off);

    __shared__ float warp_sums[8];
    const int lane = threadIdx.x & 31;
    const int wid  = threadIdx.x >> 5;
    if (lane == 0) warp_sums[wid] = partial;
    __syncthreads();

    if (wid == 0) {
        float v = (lane < 8) ? warp_sums[lane] : 0.0f;
        #pragma unroll
        for (int off = 4; off > 0; off >>= 1)
            v += __shfl_xor_sync(0xFFFFFFFFu, v, off);
        if (lane == 0)
            atomicAdd(out, v);
    }
}

extern "C" void kernel_launch(void* const* d_in, const int* in_sizes, int n_in,
                              void* d_out, int out_size)
{
    const float* pred = (const float*)d_in[0];
    float* out = (float*)d_out;

    zero_out_kernel<<<1, 1>>>(out);

    const int total_tiles = BATCH * (H / 8) * (W / 8);   // 1,048,576
    const int threads = 256;
    const int blocks = total_tiles / threads;            // 4096
    wavelet_prior_kernel<<<blocks, threads>>>(pred, out);
}